// round 4
// baseline (speedup 1.0000x reference)
#include <cuda_runtime.h>
#include <cuda_bf16.h>
#include <cstdint>
#include <math.h>

#define NS    4096
#define NTOT  8192
#define DIM   512
#define BM    128
#define BN    256
#define BK    32
#define NKC   (DIM / BK)      // 16 k-chunks
#define SQRT2F 1.41421356237f

#define ASTAGE 8192           // 128 rows * 64B
#define BSTAGE 16384          // 256 rows * 64B
#define STAGE_BYTES (ASTAGE + BSTAGE)
#define NSTAGE 3
#define SMEM_DYN (NSTAGE * STAGE_BYTES)

// ---------------- scratch (__device__ globals; no allocation allowed) -------
__device__ __align__(16) __nv_bfloat16 g_Y[NTOT * DIM];  // normalized * sqrt(2), bf16
__device__ float g_inv_norm[NTOT];
__device__ float g_row_exp[NTOT];
__device__ float g_row_sim[NTOT];   // exact fp32: full row sum - diag (pos subtracted later)
__device__ float g_spos[NTOT];
__device__ float g_S[DIM];          // colsum of fp32 normalized rows
__device__ float g_acc[3];          // final scalar accumulators

// ---------------- PTX helpers (baseline PTX only; no sm_103a features) ------
__device__ __forceinline__ uint32_t smem_u32(const void* p) {
    uint32_t a;
    asm("{ .reg .u64 t; cvta.to.shared.u64 t, %1; cvt.u32.u64 %0, t; }" : "=r"(a) : "l"(p));
    return a;
}
__device__ __forceinline__ void cp16(uint32_t dst, const void* src) {
    asm volatile("cp.async.cg.shared.global [%0], [%1], 16;" :: "r"(dst), "l"(src) : "memory");
}
__device__ __forceinline__ void ldm_x4(uint32_t* r, uint32_t addr) {
    asm volatile("ldmatrix.sync.aligned.m8n8.x4.shared.b16 {%0,%1,%2,%3}, [%4];"
                 : "=r"(r[0]), "=r"(r[1]), "=r"(r[2]), "=r"(r[3]) : "r"(addr));
}
__device__ __forceinline__ void mma16816(float* d, const uint32_t* a, const uint32_t* b) {
    asm volatile(
        "mma.sync.aligned.m16n8k16.row.col.f32.bf16.bf16.f32 "
        "{%0,%1,%2,%3}, {%4,%5,%6,%7}, {%8,%9}, {%0,%1,%2,%3};"
        : "+f"(d[0]), "+f"(d[1]), "+f"(d[2]), "+f"(d[3])
        : "r"(a[0]), "r"(a[1]), "r"(a[2]), "r"(a[3]), "r"(b[0]), "r"(b[1]));
}
// Swizzled smem offset: row r of 64B (4x16B chunks), chunk c; conflict-free
// for ldmatrix 8-row phases (verified in R3).
__device__ __forceinline__ uint32_t swz(int r, int c) {
    return (uint32_t)(r * 64 + ((c ^ ((r >> 1) & 3)) << 4));
}
__device__ __forceinline__ const float* row_ptr(const float* x1, const float* x2, int r) {
    return (r < NS) ? (x1 + (size_t)r * DIM) : (x2 + (size_t)(r - NS) * DIM);
}

// ---------------- kernel 1: norms + bf16 Y + zero accumulators --------------
__global__ void prep_kernel(const float* __restrict__ x1, const float* __restrict__ x2) {
    if (blockIdx.x == 0) {             // zero S and final accumulators
        int t = threadIdx.x;
        if (t < DIM / 2) { g_S[t] = 0.f; g_S[t + DIM / 2] = 0.f; }
        if (t < 3) g_acc[t] = 0.f;
    }
    int row  = blockIdx.x * 8 + (threadIdx.x >> 5);
    int lane = threadIdx.x & 31;
    if (row >= NTOT) return;
    const float* xr = row_ptr(x1, x2, row);
    float v[DIM / 32];
    float s = 0.f;
    #pragma unroll
    for (int c = 0; c < DIM / 32; c++) {
        v[c] = xr[lane + 32 * c];
        s = fmaf(v[c], v[c], s);
    }
    #pragma unroll
    for (int o = 16; o; o >>= 1) s += __shfl_xor_sync(0xffffffffu, s, o);
    float inv = rsqrtf(s);
    if (lane == 0) {
        g_inv_norm[row] = inv;
        g_row_exp[row]  = 0.f;
    }
    float scale = inv * SQRT2F;
    __nv_bfloat16* yr = g_Y + (size_t)row * DIM;
    #pragma unroll
    for (int c = 0; c < DIM / 32; c++)
        yr[lane + 32 * c] = __float2bfloat16(v[c] * scale);
}

// ---------------- kernel 2: fp32 colsum S = sum_rows y_row ------------------
// grid (4, 32): bx -> 128-col group, by -> 256-row slab. 128 threads.
__global__ void colsum_kernel(const float* __restrict__ x1, const float* __restrict__ x2) {
    int col  = blockIdx.x * 128 + threadIdx.x;
    int rb   = blockIdx.y * 256;
    float s = 0.f;
    for (int r = 0; r < 256; r++) {
        int row = rb + r;
        float scale = g_inv_norm[row] * SQRT2F;
        s = fmaf(row_ptr(x1, x2, row)[col], scale, s);
    }
    atomicAdd(&g_S[col], s);
}

// ---------------- kernel 3: exact fp32 positive pairs -----------------------
__global__ void pos_kernel(const float* __restrict__ x1, const float* __restrict__ x2) {
    int row  = blockIdx.x * 8 + (threadIdx.x >> 5);
    int lane = threadIdx.x & 31;
    if (row >= NS) return;
    const float* a = x1 + (size_t)row * DIM;
    const float* b = x2 + (size_t)row * DIM;
    float s = 0.f;
    #pragma unroll
    for (int c = 0; c < DIM / 32; c++)
        s = fmaf(a[lane + 32 * c], b[lane + 32 * c], s);
    #pragma unroll
    for (int o = 16; o; o >>= 1) s += __shfl_xor_sync(0xffffffffu, s, o);
    if (lane == 0) {
        float sp = 2.0f * s * g_inv_norm[row] * g_inv_norm[row + NS];
        g_spos[row]      = sp;
        g_spos[row + NS] = sp;
    }
}

// ---------------- kernel 4: rowdot: g_row_sim = y_i . S - y_i . y_i ---------
__global__ void rowdot_kernel(const float* __restrict__ x1, const float* __restrict__ x2) {
    int row  = blockIdx.x * 8 + (threadIdx.x >> 5);
    int lane = threadIdx.x & 31;
    if (row >= NTOT) return;
    const float* xr = row_ptr(x1, x2, row);
    float scale = g_inv_norm[row] * SQRT2F;
    float d = 0.f, sii = 0.f;
    #pragma unroll
    for (int c = 0; c < DIM / 32; c++) {
        float y = xr[lane + 32 * c] * scale;
        d   = fmaf(y, g_S[lane + 32 * c], d);
        sii = fmaf(y, y, sii);
    }
    #pragma unroll
    for (int o = 16; o; o >>= 1) {
        d   += __shfl_xor_sync(0xffffffffu, d, o);
        sii += __shfl_xor_sync(0xffffffffu, sii, o);
    }
    if (lane == 0) g_row_sim[row] = d - sii;
}

// ---------------- kernel 5: HMMA GEMM + masked exp epilogue -----------------
// CTA 256 thr, 8 warps 2(m)x4(n), warp tile 64x64, BM=128 BN=256 BK=32, 3 stages.
__global__ __launch_bounds__(256, 1) void gemm_kernel() {
    extern __shared__ __align__(128) char smem[];
    __shared__ float red[BM];
    const uint32_t sb = smem_u32(smem);
    const int tid = threadIdx.x, lane = tid & 31, wid = tid >> 5;
    const int wm = wid & 1, wn = wid >> 1;
    const int row0 = blockIdx.y * BM, col0 = blockIdx.x * BN;

    // global->shared mapping
    const int arow = tid >> 1, ac0 = (tid & 1) * 2;     // A: 2 thr/row, 2 chunks each
    const char* a_gsrc = (const char*)(g_Y + (size_t)(row0 + arow) * DIM) + ac0 * 16;
    const char* b_gsrc = (const char*)(g_Y + (size_t)(col0 + tid) * DIM);  // B: 1 thr/row, 4 chunks
    const uint32_t a_d0 = swz(arow, ac0), a_d1 = swz(arow, ac0 + 1);
    const uint32_t b_d0 = swz(tid, 0), b_d1 = swz(tid, 1), b_d2 = swz(tid, 2), b_d3 = swz(tid, 3);

    float acc[4][8][4];
    #pragma unroll
    for (int mi = 0; mi < 4; mi++)
        #pragma unroll
        for (int ni = 0; ni < 8; ni++)
            #pragma unroll
            for (int c = 0; c < 4; c++) acc[mi][ni][c] = 0.f;

    // prologue: stages 0,1
    #pragma unroll
    for (int s = 0; s < 2; s++) {
        uint32_t Ab = sb + s * STAGE_BYTES, Bb = Ab + ASTAGE;
        const char* as = a_gsrc + s * 64;
        const char* bs = b_gsrc + s * 64;
        cp16(Ab + a_d0, as); cp16(Ab + a_d1, as + 16);
        cp16(Bb + b_d0, bs); cp16(Bb + b_d1, bs + 16);
        cp16(Bb + b_d2, bs + 32); cp16(Bb + b_d3, bs + 48);
        asm volatile("cp.async.commit_group;" ::: "memory");
    }

    for (int kc = 0; kc < NKC; kc++) {
        if (kc == NKC - 1) asm volatile("cp.async.wait_group 0;" ::: "memory");
        else               asm volatile("cp.async.wait_group 1;" ::: "memory");
        __syncthreads();
        if (kc + 2 < NKC) {
            uint32_t Ab = sb + ((kc + 2) % NSTAGE) * STAGE_BYTES, Bb = Ab + ASTAGE;
            const char* as = a_gsrc + (size_t)(kc + 2) * 64;
            const char* bs = b_gsrc + (size_t)(kc + 2) * 64;
            cp16(Ab + a_d0, as); cp16(Ab + a_d1, as + 16);
            cp16(Bb + b_d0, bs); cp16(Bb + b_d1, bs + 16);
            cp16(Bb + b_d2, bs + 32); cp16(Bb + b_d3, bs + 48);
            asm volatile("cp.async.commit_group;" ::: "memory");
        }
        const uint32_t Ab = sb + (kc % NSTAGE) * STAGE_BYTES, Bb = Ab + ASTAGE;
        const int lrow = (lane & 7) + ((lane >> 3) & 1) * 8;
        #pragma unroll
        for (int ks = 0; ks < 2; ks++) {
            const int lchk = ks * 2 + (lane >> 4);
            uint32_t a[4][4];
            #pragma unroll
            for (int mi = 0; mi < 4; mi++)
                ldm_x4(a[mi], Ab + swz(wm * 64 + mi * 16 + lrow, lchk));
            uint32_t b[8][2];
            #pragma unroll
            for (int np = 0; np < 4; np++) {
                uint32_t t4[4];
                ldm_x4(t4, Bb + swz(wn * 64 + np * 16 + lrow, lchk));
                b[np * 2][0]     = t4[0]; b[np * 2][1]     = t4[2];
                b[np * 2 + 1][0] = t4[1]; b[np * 2 + 1][1] = t4[3];
            }
            #pragma unroll
            for (int mi = 0; mi < 4; mi++)
                #pragma unroll
                for (int ni = 0; ni < 8; ni++)
                    mma16816(acc[mi][ni], a[mi], b[ni]);
        }
    }

    // ---- epilogue: mask + exp + per-row sums -> shared -> one atomic/row ----
    if (tid < BM) red[tid] = 0.f;
    __syncthreads();

    const int rloc = wm * 64 + (lane >> 2);               // local row base
    const int cbase = col0 + wn * 64 + 2 * (lane & 3);
    #pragma unroll
    for (int mi = 0; mi < 4; mi++) {
        #pragma unroll
        for (int h = 0; h < 2; h++) {
            const int il = rloc + mi * 16 + h * 8;
            const int i  = row0 + il;
            float e = 0.f;
            #pragma unroll
            for (int ni = 0; ni < 8; ni++) {
                #pragma unroll
                for (int q = 0; q < 2; q++) {
                    const int j = cbase + ni * 8 + q;
                    float s = acc[mi][ni][h * 2 + q];
                    if (((i ^ j) & (NS - 1)) != 0) e += __expf(s);
                }
            }
            e += __shfl_xor_sync(0xffffffffu, e, 1);
            e += __shfl_xor_sync(0xffffffffu, e, 2);
            if ((lane & 3) == 0) atomicAdd(&red[il], e);
        }
    }
    __syncthreads();
    if (tid < BM) atomicAdd(&g_row_exp[row0 + tid], red[tid]);
}

// ---------------- kernel 6a/6b: parallel finalize ---------------------------
__global__ void finalize_partial(void) {
    int i = blockIdx.x * 512 + threadIdx.x;
    float sp    = g_spos[i];
    float denom = __expf(sp) + g_row_exp[i] + 2.0f;  // +2 = exp(0) at 2 masked entries
    float l     = __logf(denom) - sp;
    float nsum  = g_row_sim[i] - sp;                 // exclude positive pair
    #pragma unroll
    for (int o = 16; o; o >>= 1) {
        l    += __shfl_xor_sync(0xffffffffu, l, o);
        sp   += __shfl_xor_sync(0xffffffffu, sp, o);
        nsum += __shfl_xor_sync(0xffffffffu, nsum, o);
    }
    __shared__ float r[48];
    int w = threadIdx.x >> 5, lane = threadIdx.x & 31;
    if (lane == 0) { r[w] = l; r[16 + w] = sp; r[32 + w] = nsum; }
    __syncthreads();
    if (threadIdx.x == 0) {
        float L = 0.f, P = 0.f, NN = 0.f;
        for (int k = 0; k < 16; k++) { L += r[k]; P += r[16 + k]; NN += r[32 + k]; }
        atomicAdd(&g_acc[0], L);
        atomicAdd(&g_acc[1], P);
        atomicAdd(&g_acc[2], NN);
    }
}
__global__ void finalize_write(float* __restrict__ out) {
    out[0] = g_acc[0] / (float)NTOT;
    out[1] = g_acc[1] / (float)NTOT;
    out[2] = g_acc[2] / (float)((double)NTOT * (double)NTOT - 2.0 * (double)NTOT);
}

extern "C" void kernel_launch(void* const* d_in, const int* in_sizes, int n_in,
                              void* d_out, int out_size) {
    const float* x1 = (const float*)d_in[0];
    const float* x2 = (const float*)d_in[1];
    cudaFuncSetAttribute(gemm_kernel, cudaFuncAttributeMaxDynamicSharedMemorySize, SMEM_DYN);
    prep_kernel<<<NTOT / 8, 256>>>(x1, x2);
    colsum_kernel<<<dim3(4, 32), 128>>>(x1, x2);
    pos_kernel<<<NS / 8, 256>>>(x1, x2);
    rowdot_kernel<<<NTOT / 8, 256>>>(x1, x2);
    gemm_kernel<<<dim3(NTOT / BN, NTOT / BM), 256, SMEM_DYN>>>();
    finalize_partial<<<16, 512>>>();
    finalize_write<<<1, 1>>>((float*)d_out);
}

// round 5
// speedup vs baseline: 1.5027x; 1.5027x over previous
#include <cuda_runtime.h>
#include <cuda_bf16.h>
#include <cstdint>
#include <math.h>

#define NS    4096
#define NTOT  8192
#define DIM   512
#define BM    128
#define BN    128
#define BKB   64              // k-chunk in bytes (= 64 fp8 elems)
#define NKC   (DIM / BKB)     // 8 k-chunks
#define SQRT2F 1.41421356237f
#define STAGE_BYTES 16384     // A 8KB + B 8KB

// ---------------- scratch (__device__ globals; no allocation allowed) -------
__device__ __align__(16) uint8_t g_Yq[NTOT * DIM];   // e4m3(normalized * sqrt2)
__device__ float g_inv_norm[NTOT];
__device__ float g_row_exp[NTOT];
__device__ float g_posdot[NS];      // raw fp32 dot(x1_r, x2_r)
__device__ float g_S[DIM];          // fp32 colsum of normalized rows
__device__ float g_acc[3];

// ---------------- PTX helpers (baseline PTX only) ---------------------------
__device__ __forceinline__ uint32_t smem_u32(const void* p) {
    uint32_t a;
    asm("{ .reg .u64 t; cvta.to.shared.u64 t, %1; cvt.u32.u64 %0, t; }" : "=r"(a) : "l"(p));
    return a;
}
__device__ __forceinline__ void cp16(uint32_t dst, const void* src) {
    asm volatile("cp.async.cg.shared.global [%0], [%1], 16;" :: "r"(dst), "l"(src) : "memory");
}
__device__ __forceinline__ void ldm_x4(uint32_t* r, uint32_t addr) {
    asm volatile("ldmatrix.sync.aligned.m8n8.x4.shared.b16 {%0,%1,%2,%3}, [%4];"
                 : "=r"(r[0]), "=r"(r[1]), "=r"(r[2]), "=r"(r[3]) : "r"(addr));
}
__device__ __forceinline__ void mma_fp8(float* d, const uint32_t* a, const uint32_t* b) {
    asm volatile(
        "mma.sync.aligned.m16n8k32.row.col.f32.e4m3.e4m3.f32 "
        "{%0,%1,%2,%3}, {%4,%5,%6,%7}, {%8,%9}, {%0,%1,%2,%3};"
        : "+f"(d[0]), "+f"(d[1]), "+f"(d[2]), "+f"(d[3])
        : "r"(a[0]), "r"(a[1]), "r"(a[2]), "r"(a[3]), "r"(b[0]), "r"(b[1]));
}
__device__ __forceinline__ uint16_t f2_e4m3x2(float lo, float hi) {
    uint16_t r;
    asm("cvt.rn.satfinite.e4m3x2.f32 %0, %1, %2;" : "=h"(r) : "f"(hi), "f"(lo));
    return r;
}
// Swizzled smem offset: row r of 64B (4x16B chunks), chunk c; conflict-free
// for the ldmatrix phases used below (validated in R3).
__device__ __forceinline__ uint32_t swz(int r, int c) {
    return (uint32_t)(r * 64 + ((c ^ ((r >> 1) & 3)) << 4));
}
__device__ __forceinline__ const float* row_ptr(const float* x1, const float* x2, int r) {
    return (r < NS) ? (x1 + (size_t)r * DIM) : (x2 + (size_t)(r - NS) * DIM);
}

// ---------------- kernel 1: norms + fp8 Y + posdot + zero accums ------------
__global__ void prep_kernel(const float* __restrict__ x1, const float* __restrict__ x2) {
    if (blockIdx.x == 0) {
        int t = threadIdx.x;
        g_S[t] = 0.f; g_S[t + 256] = 0.f;
        if (t < 3) g_acc[t] = 0.f;
    }
    int row  = blockIdx.x * 8 + (threadIdx.x >> 5);
    int lane = threadIdx.x & 31;
    if (row >= NTOT) return;
    const float4* xr = (const float4*)row_ptr(x1, x2, row);
    float4 v[4];
    float s = 0.f;
    #pragma unroll
    for (int c = 0; c < 4; c++) {
        v[c] = xr[lane + 32 * c];
        s += v[c].x * v[c].x + v[c].y * v[c].y + v[c].z * v[c].z + v[c].w * v[c].w;
    }
    // positive-pair raw dot (rows < NS pair with row+NS)
    float pd = 0.f;
    if (row < NS) {
        const float4* wr = (const float4*)(x2 + (size_t)row * DIM);
        #pragma unroll
        for (int c = 0; c < 4; c++) {
            float4 w = wr[lane + 32 * c];
            pd += v[c].x * w.x + v[c].y * w.y + v[c].z * w.z + v[c].w * w.w;
        }
    }
    #pragma unroll
    for (int o = 16; o; o >>= 1) {
        s  += __shfl_xor_sync(0xffffffffu, s, o);
        pd += __shfl_xor_sync(0xffffffffu, pd, o);
    }
    float inv = rsqrtf(s);
    if (lane == 0) {
        g_inv_norm[row] = inv;
        g_row_exp[row]  = 0.f;
        if (row < NS) g_posdot[row] = pd;
    }
    float scale = inv * SQRT2F;
    uint32_t* yq = (uint32_t*)(g_Yq + (size_t)row * DIM);
    #pragma unroll
    for (int c = 0; c < 4; c++) {
        uint32_t lo = f2_e4m3x2(v[c].x * scale, v[c].y * scale);
        uint32_t hi = f2_e4m3x2(v[c].z * scale, v[c].w * scale);
        yq[lane + 32 * c] = lo | (hi << 16);
    }
}

// ---------------- kernel 2: fp32 colsum S = sum_rows y_row ------------------
__global__ void colsum_kernel(const float* __restrict__ x1, const float* __restrict__ x2) {
    int col = blockIdx.x * 128 + threadIdx.x;
    int rb  = blockIdx.y * 256;
    float s = 0.f;
    #pragma unroll 4
    for (int r = 0; r < 256; r++) {
        int row = rb + r;
        s = fmaf(row_ptr(x1, x2, row)[col], g_inv_norm[row] * SQRT2F, s);
    }
    atomicAdd(&g_S[col], s);
}

// ---------------- kernel 3: fp8 QMMA GEMM + masked exp epilogue -------------
// 128x128 tile, 8 warps as 4(m) x 2(n): warp tile 32m x 64n.  (R3 structure)
__global__ __launch_bounds__(256, 2) void gemm_kernel() {
    __shared__ __align__(128) char smem[2 * STAGE_BYTES];
    __shared__ float red[BM];
    const uint32_t sb = smem_u32(smem);
    const int tid  = threadIdx.x, lane = tid & 31, wid = tid >> 5;
    const int wm   = wid & 3, wn = wid >> 2;
    const int row0 = blockIdx.y * BM, col0 = blockIdx.x * BN;

    // Global->shared: 2 threads/row, 2x16B each (A and B identical pattern)
    const int lr  = tid >> 1;
    const int lc0 = (tid & 1) * 2;
    const char* a_gsrc = (const char*)(g_Yq + (size_t)(row0 + lr) * DIM) + lc0 * 16;
    const char* b_gsrc = (const char*)(g_Yq + (size_t)(col0 + lr) * DIM) + lc0 * 16;
    const uint32_t adst0 = swz(lr, lc0), adst1 = swz(lr, lc0 + 1);

    float acc[2][8][4];
    #pragma unroll
    for (int mi = 0; mi < 2; mi++)
        #pragma unroll
        for (int ni = 0; ni < 8; ni++)
            #pragma unroll
            for (int c = 0; c < 4; c++) acc[mi][ni][c] = 0.f;

    // prologue: stage 0
    {
        uint32_t Ab = sb, Bb = sb + 8192;
        cp16(Ab + adst0, a_gsrc);
        cp16(Ab + adst1, a_gsrc + 16);
        cp16(Bb + adst0, b_gsrc);
        cp16(Bb + adst1, b_gsrc + 16);
        asm volatile("cp.async.commit_group;" ::: "memory");
    }

    for (int kc = 0; kc < NKC; kc++) {
        if (kc + 1 < NKC) {
            uint32_t Ab = sb + ((kc + 1) & 1) * STAGE_BYTES, Bb = Ab + 8192;
            const char* as = a_gsrc + (size_t)(kc + 1) * BKB;
            const char* bs = b_gsrc + (size_t)(kc + 1) * BKB;
            cp16(Ab + adst0, as);
            cp16(Ab + adst1, as + 16);
            cp16(Bb + adst0, bs);
            cp16(Bb + adst1, bs + 16);
            asm volatile("cp.async.commit_group;" ::: "memory");
            asm volatile("cp.async.wait_group 1;" ::: "memory");
        } else {
            asm volatile("cp.async.wait_group 0;" ::: "memory");
        }
        __syncthreads();

        const uint32_t Ab = sb + (kc & 1) * STAGE_BYTES, Bb = Ab + 8192;
        const int lrow = (lane & 7) + ((lane >> 3) & 1) * 8;
        #pragma unroll
        for (int ks = 0; ks < 2; ks++) {        // two k32 steps per 64B chunk
            const int lchk = ks * 2 + (lane >> 4);
            uint32_t a[2][4];
            #pragma unroll
            for (int mi = 0; mi < 2; mi++)
                ldm_x4(a[mi], Ab + swz(wm * 32 + mi * 16 + lrow, lchk));
            uint32_t b[8][2];
            #pragma unroll
            for (int np = 0; np < 4; np++) {
                uint32_t t4[4];
                ldm_x4(t4, Bb + swz(wn * 64 + np * 16 + lrow, lchk));
                b[np * 2][0]     = t4[0]; b[np * 2][1]     = t4[2];
                b[np * 2 + 1][0] = t4[1]; b[np * 2 + 1][1] = t4[3];
            }
            #pragma unroll
            for (int mi = 0; mi < 2; mi++)
                #pragma unroll
                for (int ni = 0; ni < 8; ni++)
                    mma_fp8(acc[mi][ni], a[mi], b[ni]);
        }
        __syncthreads();
    }

    // ---- epilogue: mask + exp + per-row sums -> shared -> one atomic/row ----
    if (tid < BM) red[tid] = 0.f;
    __syncthreads();
    const int rloc  = wm * 32 + (lane >> 2);
    const int cbase = col0 + wn * 64 + 2 * (lane & 3);
    #pragma unroll
    for (int mi = 0; mi < 2; mi++) {
        #pragma unroll
        for (int h = 0; h < 2; h++) {
            const int il = rloc + mi * 16 + h * 8;
            const int i  = row0 + il;
            float e = 0.f;
            #pragma unroll
            for (int ni = 0; ni < 8; ni++) {
                #pragma unroll
                for (int q = 0; q < 2; q++) {
                    const int j = cbase + ni * 8 + q;
                    float s = acc[mi][ni][h * 2 + q];
                    if (((i ^ j) & (NS - 1)) != 0) e += __expf(s);
                }
            }
            e += __shfl_xor_sync(0xffffffffu, e, 1);
            e += __shfl_xor_sync(0xffffffffu, e, 2);
            if ((lane & 3) == 0) atomicAdd(&red[il], e);
        }
    }
    __syncthreads();
    if (tid < BM) atomicAdd(&g_row_exp[row0 + tid], red[tid]);
}

// ---------------- kernel 4: per-row finalize (rowdot + loss) ----------------
__global__ void final_row_kernel(const float* __restrict__ x1, const float* __restrict__ x2) {
    __shared__ float r[24];
    int row  = blockIdx.x * 8 + (threadIdx.x >> 5);
    int wid  = threadIdx.x >> 5;
    int lane = threadIdx.x & 31;
    float scale = g_inv_norm[row] * SQRT2F;
    const float4* xr = (const float4*)row_ptr(x1, x2, row);
    const float4* S4 = (const float4*)g_S;
    float d = 0.f, sii = 0.f;
    #pragma unroll
    for (int c = 0; c < 4; c++) {
        float4 v = xr[lane + 32 * c];
        float4 sc = S4[lane + 32 * c];
        float4 y = make_float4(v.x * scale, v.y * scale, v.z * scale, v.w * scale);
        d   += y.x * sc.x + y.y * sc.y + y.z * sc.z + y.w * sc.w;
        sii += y.x * y.x + y.y * y.y + y.z * y.z + y.w * y.w;
    }
    #pragma unroll
    for (int o = 16; o; o >>= 1) {
        d   += __shfl_xor_sync(0xffffffffu, d, o);
        sii += __shfl_xor_sync(0xffffffffu, sii, o);
    }
    if (lane == 0) {
        float sp = 2.0f * g_posdot[row & (NS - 1)] * g_inv_norm[row] * g_inv_norm[row ^ NS];
        float denom = __expf(sp) + g_row_exp[row] + 2.0f;  // +2 = exp(0) at 2 masked entries
        r[wid]      = __logf(denom) - sp;                  // loss_i
        r[8 + wid]  = sp;
        r[16 + wid] = (d - sii) - sp;                      // exact neg-sim row sum
    }
    __syncthreads();
    if (threadIdx.x == 0) {
        float L = 0.f, P = 0.f, NN = 0.f;
        #pragma unroll
        for (int k = 0; k < 8; k++) { L += r[k]; P += r[8 + k]; NN += r[16 + k]; }
        atomicAdd(&g_acc[0], L);
        atomicAdd(&g_acc[1], P);
        atomicAdd(&g_acc[2], NN);
    }
}
__global__ void finalize_write(float* __restrict__ out) {
    out[0] = g_acc[0] / (float)NTOT;
    out[1] = g_acc[1] / (float)NTOT;
    out[2] = g_acc[2] / (float)((double)NTOT * (double)NTOT - 2.0 * (double)NTOT);
}

extern "C" void kernel_launch(void* const* d_in, const int* in_sizes, int n_in,
                              void* d_out, int out_size) {
    const float* x1 = (const float*)d_in[0];
    const float* x2 = (const float*)d_in[1];
    prep_kernel<<<NTOT / 8, 256>>>(x1, x2);
    colsum_kernel<<<dim3(4, 32), 128>>>(x1, x2);
    gemm_kernel<<<dim3(NTOT / BN, NTOT / BM), 256>>>();
    final_row_kernel<<<NTOT / 8, 256>>>(x1, x2);
    finalize_write<<<1, 1>>>((float*)d_out);
}

// round 6
// speedup vs baseline: 2.3625x; 1.5722x over previous
#include <cuda_runtime.h>
#include <cuda_bf16.h>
#include <cstdint>
#include <math.h>

#define NS    4096
#define NTOT  8192
#define DIM   512
#define BM    128
#define BN    128
#define BKB   64              // k-chunk in bytes (= 64 fp8 elems)
#define NKC   (DIM / BKB)     // 8 k-chunks
#define SQRT2F 1.41421356237f
#define STAGE_BYTES 16384     // A 8KB + B 8KB
#define NTILE (64 * 65 / 2)   // triangular tiles

// ---------------- scratch (__device__ globals; no allocation allowed) -------
__device__ __align__(16) uint8_t g_Yq[NTOT * DIM];   // e4m3(normalized * sqrt2)
__device__ float g_inv_norm[NTOT];
__device__ float g_row_exp[NTOT];
__device__ float g_posdot[NS];      // raw fp32 dot(x1_r, x2_r)
__device__ float g_S[DIM];          // fp32 colsum of normalized rows
__device__ float g_acc[3];

// ---------------- PTX helpers (baseline PTX only) ---------------------------
__device__ __forceinline__ uint32_t smem_u32(const void* p) {
    uint32_t a;
    asm("{ .reg .u64 t; cvta.to.shared.u64 t, %1; cvt.u32.u64 %0, t; }" : "=r"(a) : "l"(p));
    return a;
}
__device__ __forceinline__ void cp16(uint32_t dst, const void* src) {
    asm volatile("cp.async.cg.shared.global [%0], [%1], 16;" :: "r"(dst), "l"(src) : "memory");
}
__device__ __forceinline__ void ldm_x4(uint32_t* r, uint32_t addr) {
    asm volatile("ldmatrix.sync.aligned.m8n8.x4.shared.b16 {%0,%1,%2,%3}, [%4];"
                 : "=r"(r[0]), "=r"(r[1]), "=r"(r[2]), "=r"(r[3]) : "r"(addr));
}
__device__ __forceinline__ void mma_fp8(float* d, const uint32_t* a, const uint32_t* b) {
    asm volatile(
        "mma.sync.aligned.m16n8k32.row.col.f32.e4m3.e4m3.f32 "
        "{%0,%1,%2,%3}, {%4,%5,%6,%7}, {%8,%9}, {%0,%1,%2,%3};"
        : "+f"(d[0]), "+f"(d[1]), "+f"(d[2]), "+f"(d[3])
        : "r"(a[0]), "r"(a[1]), "r"(a[2]), "r"(a[3]), "r"(b[0]), "r"(b[1]));
}
__device__ __forceinline__ uint16_t f2_e4m3x2(float lo, float hi) {
    uint16_t r;
    asm("cvt.rn.satfinite.e4m3x2.f32 %0, %1, %2;" : "=h"(r) : "f"(hi), "f"(lo));
    return r;
}
// Swizzled smem offset: row r of 64B (4x16B chunks), chunk c; conflict-free
// for the ldmatrix phases used below (validated in R3/R5).
__device__ __forceinline__ uint32_t swz(int r, int c) {
    return (uint32_t)(r * 64 + ((c ^ ((r >> 1) & 3)) << 4));
}
__device__ __forceinline__ const float* row_ptr(const float* x1, const float* x2, int r) {
    return (r < NS) ? (x1 + (size_t)r * DIM) : (x2 + (size_t)(r - NS) * DIM);
}

// ---------------- kernel 1: norms + fp8 Y + posdot + zero accums ------------
__global__ void prep_kernel(const float* __restrict__ x1, const float* __restrict__ x2) {
    if (blockIdx.x == 0) {
        int t = threadIdx.x;
        g_S[t] = 0.f; g_S[t + 256] = 0.f;
        if (t < 3) g_acc[t] = 0.f;
    }
    int row  = blockIdx.x * 8 + (threadIdx.x >> 5);
    int lane = threadIdx.x & 31;
    if (row >= NTOT) return;
    const float4* xr = (const float4*)row_ptr(x1, x2, row);
    float4 v[4];
    float s = 0.f;
    #pragma unroll
    for (int c = 0; c < 4; c++) {
        v[c] = xr[lane + 32 * c];
        s += v[c].x * v[c].x + v[c].y * v[c].y + v[c].z * v[c].z + v[c].w * v[c].w;
    }
    float pd = 0.f;
    if (row < NS) {
        const float4* wr = (const float4*)(x2 + (size_t)row * DIM);
        #pragma unroll
        for (int c = 0; c < 4; c++) {
            float4 w = wr[lane + 32 * c];
            pd += v[c].x * w.x + v[c].y * w.y + v[c].z * w.z + v[c].w * w.w;
        }
    }
    #pragma unroll
    for (int o = 16; o; o >>= 1) {
        s  += __shfl_xor_sync(0xffffffffu, s, o);
        pd += __shfl_xor_sync(0xffffffffu, pd, o);
    }
    float inv = rsqrtf(s);
    if (lane == 0) {
        g_inv_norm[row] = inv;
        g_row_exp[row]  = 0.f;
        if (row < NS) g_posdot[row] = pd;
    }
    float scale = inv * SQRT2F;
    uint32_t* yq = (uint32_t*)(g_Yq + (size_t)row * DIM);
    #pragma unroll
    for (int c = 0; c < 4; c++) {
        uint32_t lo = f2_e4m3x2(v[c].x * scale, v[c].y * scale);
        uint32_t hi = f2_e4m3x2(v[c].z * scale, v[c].w * scale);
        yq[lane + 32 * c] = lo | (hi << 16);
    }
}

// ---------------- kernel 2: fp32 colsum S = sum_rows y_row ------------------
__global__ void colsum_kernel(const float* __restrict__ x1, const float* __restrict__ x2) {
    int col = blockIdx.x * 128 + threadIdx.x;
    int rb  = blockIdx.y * 256;
    float s = 0.f;
    #pragma unroll 4
    for (int r = 0; r < 256; r++) {
        int row = rb + r;
        s = fmaf(row_ptr(x1, x2, row)[col], g_inv_norm[row] * SQRT2F, s);
    }
    atomicAdd(&g_S[col], s);
}

// ---------------- kernel 3: fp8 GEMM on UPPER-TRIANGULAR tiles --------------
// Off-diag tile (R<C): each exp(s_ij) feeds row_exp[i] AND row_exp[j] (symmetry).
// Diag tile: rows-only is complete (tile contains both (i,j) and (j,i)).
__global__ __launch_bounds__(256, 2) void gemm_kernel() {
    __shared__ __align__(128) char smem[2 * STAGE_BYTES];
    __shared__ float red[BM];    // per-row partials
    __shared__ float cred[BN];   // per-col partials (off-diag only)
    const uint32_t sb = smem_u32(smem);
    const int tid  = threadIdx.x, lane = tid & 31, wid = tid >> 5;
    const int wm   = wid & 3, wn = wid >> 2;

    // triangular decode: k -> (bx, by), by <= bx
    const int k = blockIdx.x;
    int bx = (int)((sqrtf(8.0f * (float)k + 1.0f) - 1.0f) * 0.5f);
    while ((bx + 1) * (bx + 2) / 2 <= k) bx++;
    while (bx * (bx + 1) / 2 > k)       bx--;
    const int by = k - bx * (bx + 1) / 2;
    const int row0 = by * BM, col0 = bx * BN;
    const bool offdiag = (bx != by);

    const int lr  = tid >> 1;
    const int lc0 = (tid & 1) * 2;
    const char* a_gsrc = (const char*)(g_Yq + (size_t)(row0 + lr) * DIM) + lc0 * 16;
    const char* b_gsrc = (const char*)(g_Yq + (size_t)(col0 + lr) * DIM) + lc0 * 16;
    const uint32_t adst0 = swz(lr, lc0), adst1 = swz(lr, lc0 + 1);

    float acc[2][8][4];
    #pragma unroll
    for (int mi = 0; mi < 2; mi++)
        #pragma unroll
        for (int ni = 0; ni < 8; ni++)
            #pragma unroll
            for (int c = 0; c < 4; c++) acc[mi][ni][c] = 0.f;

    {
        uint32_t Ab = sb, Bb = sb + 8192;
        cp16(Ab + adst0, a_gsrc);
        cp16(Ab + adst1, a_gsrc + 16);
        cp16(Bb + adst0, b_gsrc);
        cp16(Bb + adst1, b_gsrc + 16);
        asm volatile("cp.async.commit_group;" ::: "memory");
    }

    for (int kc = 0; kc < NKC; kc++) {
        if (kc + 1 < NKC) {
            uint32_t Ab = sb + ((kc + 1) & 1) * STAGE_BYTES, Bb = Ab + 8192;
            const char* as = a_gsrc + (size_t)(kc + 1) * BKB;
            const char* bs = b_gsrc + (size_t)(kc + 1) * BKB;
            cp16(Ab + adst0, as);
            cp16(Ab + adst1, as + 16);
            cp16(Bb + adst0, bs);
            cp16(Bb + adst1, bs + 16);
            asm volatile("cp.async.commit_group;" ::: "memory");
            asm volatile("cp.async.wait_group 1;" ::: "memory");
        } else {
            asm volatile("cp.async.wait_group 0;" ::: "memory");
        }
        __syncthreads();

        const uint32_t Ab = sb + (kc & 1) * STAGE_BYTES, Bb = Ab + 8192;
        const int lrow = (lane & 7) + ((lane >> 3) & 1) * 8;
        #pragma unroll
        for (int ks = 0; ks < 2; ks++) {
            const int lchk = ks * 2 + (lane >> 4);
            uint32_t a[2][4];
            #pragma unroll
            for (int mi = 0; mi < 2; mi++)
                ldm_x4(a[mi], Ab + swz(wm * 32 + mi * 16 + lrow, lchk));
            uint32_t b[8][2];
            #pragma unroll
            for (int np = 0; np < 4; np++) {
                uint32_t t4[4];
                ldm_x4(t4, Bb + swz(wn * 64 + np * 16 + lrow, lchk));
                b[np * 2][0]     = t4[0]; b[np * 2][1]     = t4[2];
                b[np * 2 + 1][0] = t4[1]; b[np * 2 + 1][1] = t4[3];
            }
            #pragma unroll
            for (int mi = 0; mi < 2; mi++)
                #pragma unroll
                for (int ni = 0; ni < 8; ni++)
                    mma_fp8(acc[mi][ni], a[mi], b[ni]);
        }
        __syncthreads();
    }

    // ---- epilogue: exp once, feed row partials (+ col partials if offdiag) --
    if (tid < BM) { red[tid] = 0.f; cred[tid] = 0.f; }
    __syncthreads();
    const int rloc  = wm * 32 + (lane >> 2);
    const int cbase = col0 + wn * 64 + 2 * (lane & 3);
    float ccol[16];
    #pragma unroll
    for (int t = 0; t < 16; t++) ccol[t] = 0.f;

    #pragma unroll
    for (int mi = 0; mi < 2; mi++) {
        #pragma unroll
        for (int h = 0; h < 2; h++) {
            const int il = rloc + mi * 16 + h * 8;
            const int i  = row0 + il;
            float e = 0.f;
            #pragma unroll
            for (int ni = 0; ni < 8; ni++) {
                #pragma unroll
                for (int q = 0; q < 2; q++) {
                    const int j = cbase + ni * 8 + q;
                    float s = acc[mi][ni][h * 2 + q];
                    float ex = (((i ^ j) & (NS - 1)) != 0) ? __expf(s) : 0.f;
                    e += ex;
                    ccol[ni * 2 + q] += ex;
                }
            }
            e += __shfl_xor_sync(0xffffffffu, e, 1);
            e += __shfl_xor_sync(0xffffffffu, e, 2);
            if ((lane & 3) == 0) atomicAdd(&red[il], e);
        }
    }
    if (offdiag) {
        #pragma unroll
        for (int ni = 0; ni < 8; ni++) {
            #pragma unroll
            for (int q = 0; q < 2; q++) {
                float c = ccol[ni * 2 + q];
                c += __shfl_xor_sync(0xffffffffu, c, 4);
                c += __shfl_xor_sync(0xffffffffu, c, 8);
                c += __shfl_xor_sync(0xffffffffu, c, 16);
                if ((lane >> 2) == 0)                       // lanes 0..3
                    atomicAdd(&cred[wn * 64 + ni * 8 + 2 * lane + q], c);
            }
        }
    }
    __syncthreads();
    if (tid < BM) {
        atomicAdd(&g_row_exp[row0 + tid], red[tid]);
        if (offdiag) atomicAdd(&g_row_exp[col0 + tid], cred[tid]);
    }
}

// ---------------- kernel 4: per-row finalize (rowdot + loss) ----------------
__global__ void final_row_kernel(const float* __restrict__ x1, const float* __restrict__ x2) {
    __shared__ float r[24];
    int row  = blockIdx.x * 8 + (threadIdx.x >> 5);
    int wid  = threadIdx.x >> 5;
    int lane = threadIdx.x & 31;
    float scale = g_inv_norm[row] * SQRT2F;
    const float4* xr = (const float4*)row_ptr(x1, x2, row);
    const float4* S4 = (const float4*)g_S;
    float d = 0.f, sii = 0.f;
    #pragma unroll
    for (int c = 0; c < 4; c++) {
        float4 v = xr[lane + 32 * c];
        float4 sc = S4[lane + 32 * c];
        float4 y = make_float4(v.x * scale, v.y * scale, v.z * scale, v.w * scale);
        d   += y.x * sc.x + y.y * sc.y + y.z * sc.z + y.w * sc.w;
        sii += y.x * y.x + y.y * y.y + y.z * y.z + y.w * y.w;
    }
    #pragma unroll
    for (int o = 16; o; o >>= 1) {
        d   += __shfl_xor_sync(0xffffffffu, d, o);
        sii += __shfl_xor_sync(0xffffffffu, sii, o);
    }
    if (lane == 0) {
        float sp = 2.0f * g_posdot[row & (NS - 1)] * g_inv_norm[row] * g_inv_norm[row ^ NS];
        float denom = __expf(sp) + g_row_exp[row] + 2.0f;  // +2 = exp(0) at 2 masked entries
        r[wid]      = __logf(denom) - sp;
        r[8 + wid]  = sp;
        r[16 + wid] = (d - sii) - sp;                      // exact neg-sim row sum
    }
    __syncthreads();
    if (threadIdx.x == 0) {
        float L = 0.f, P = 0.f, NN = 0.f;
        #pragma unroll
        for (int k = 0; k < 8; k++) { L += r[k]; P += r[8 + k]; NN += r[16 + k]; }
        atomicAdd(&g_acc[0], L);
        atomicAdd(&g_acc[1], P);
        atomicAdd(&g_acc[2], NN);
    }
}
__global__ void finalize_write(float* __restrict__ out) {
    out[0] = g_acc[0] / (float)NTOT;
    out[1] = g_acc[1] / (float)NTOT;
    out[2] = g_acc[2] / (float)((double)NTOT * (double)NTOT - 2.0 * (double)NTOT);
}

extern "C" void kernel_launch(void* const* d_in, const int* in_sizes, int n_in,
                              void* d_out, int out_size) {
    const float* x1 = (const float*)d_in[0];
    const float* x2 = (const float*)d_in[1];
    prep_kernel<<<NTOT / 8, 256>>>(x1, x2);
    colsum_kernel<<<dim3(4, 32), 128>>>(x1, x2);
    gemm_kernel<<<NTILE, 256>>>();
    final_row_kernel<<<NTOT / 8, 256>>>(x1, x2);
    finalize_write<<<1, 1>>>((float*)d_out);
}

// round 7
// speedup vs baseline: 2.4092x; 1.0198x over previous
#include <cuda_runtime.h>
#include <cuda_bf16.h>
#include <cstdint>
#include <math.h>

#define NS    4096
#define NTOT  8192
#define DIM   512
#define BM    128
#define BN    128
#define BKB   64              // k-chunk in bytes (= 64 fp8 elems)
#define NKC   (DIM / BKB)     // 8 k-chunks
#define SQRT2F 1.41421356237f
#define STAGE_BYTES 16384     // A 8KB + B 8KB
#define NSTAGE 3
#define SMEM_DYN (NSTAGE * STAGE_BYTES)
#define NTILE (64 * 65 / 2)   // triangular tiles

// ---------------- scratch (__device__ globals; no allocation allowed) -------
__device__ __align__(16) uint8_t g_Yq[NTOT * DIM];   // e4m3(normalized * sqrt2)
__device__ float g_inv_norm[NTOT];
__device__ float g_row_exp[NTOT];
__device__ float g_posdot[NS];      // raw fp32 dot(x1_r, x2_r)
__device__ float g_S[DIM];          // fp32 colsum of normalized rows
__device__ float g_acc[3];

// ---------------- PTX helpers (baseline PTX only) ---------------------------
__device__ __forceinline__ uint32_t smem_u32(const void* p) {
    uint32_t a;
    asm("{ .reg .u64 t; cvta.to.shared.u64 t, %1; cvt.u32.u64 %0, t; }" : "=r"(a) : "l"(p));
    return a;
}
__device__ __forceinline__ void cp16(uint32_t dst, const void* src) {
    asm volatile("cp.async.cg.shared.global [%0], [%1], 16;" :: "r"(dst), "l"(src) : "memory");
}
__device__ __forceinline__ void ldm_x4(uint32_t* r, uint32_t addr) {
    asm volatile("ldmatrix.sync.aligned.m8n8.x4.shared.b16 {%0,%1,%2,%3}, [%4];"
                 : "=r"(r[0]), "=r"(r[1]), "=r"(r[2]), "=r"(r[3]) : "r"(addr));
}
__device__ __forceinline__ void mma_fp8(float* d, const uint32_t* a, const uint32_t* b) {
    asm volatile(
        "mma.sync.aligned.m16n8k32.row.col.f32.e4m3.e4m3.f32 "
        "{%0,%1,%2,%3}, {%4,%5,%6,%7}, {%8,%9}, {%0,%1,%2,%3};"
        : "+f"(d[0]), "+f"(d[1]), "+f"(d[2]), "+f"(d[3])
        : "r"(a[0]), "r"(a[1]), "r"(a[2]), "r"(a[3]), "r"(b[0]), "r"(b[1]));
}
__device__ __forceinline__ uint16_t f2_e4m3x2(float lo, float hi) {
    uint16_t r;
    asm("cvt.rn.satfinite.e4m3x2.f32 %0, %1, %2;" : "=h"(r) : "f"(hi), "f"(lo));
    return r;
}
// Swizzled smem offset: row r of 64B (4x16B chunks), chunk c; conflict-free
// for the ldmatrix phases used below (validated R3/R5/R6).
__device__ __forceinline__ uint32_t swz(int r, int c) {
    return (uint32_t)(r * 64 + ((c ^ ((r >> 1) & 3)) << 4));
}
__device__ __forceinline__ const float* row_ptr(const float* x1, const float* x2, int r) {
    return (r < NS) ? (x1 + (size_t)r * DIM) : (x2 + (size_t)(r - NS) * DIM);
}

// ---------------- kernel 0: zero global accumulators (every replay) ---------
__global__ void zero_kernel() {
    int t = threadIdx.x;
    if (t < DIM) g_S[t] = 0.f;
    if (t < 3)   g_acc[t] = 0.f;
}

// ---------------- kernel 1: norms + fp8 Y + posdot + fused colsum -----------
__global__ void prep_kernel(const float* __restrict__ x1, const float* __restrict__ x2) {
    __shared__ float sY[8][DIM];
    int wid  = threadIdx.x >> 5;
    int lane = threadIdx.x & 31;
    int row  = blockIdx.x * 8 + wid;
    const float4* xr = (const float4*)row_ptr(x1, x2, row);
    float4 v[4];
    float s = 0.f;
    #pragma unroll
    for (int c = 0; c < 4; c++) {
        v[c] = xr[lane + 32 * c];
        s += v[c].x * v[c].x + v[c].y * v[c].y + v[c].z * v[c].z + v[c].w * v[c].w;
    }
    float pd = 0.f;
    if (row < NS) {
        const float4* wr = (const float4*)(x2 + (size_t)row * DIM);
        #pragma unroll
        for (int c = 0; c < 4; c++) {
            float4 w = wr[lane + 32 * c];
            pd += v[c].x * w.x + v[c].y * w.y + v[c].z * w.z + v[c].w * w.w;
        }
    }
    #pragma unroll
    for (int o = 16; o; o >>= 1) {
        s  += __shfl_xor_sync(0xffffffffu, s, o);
        pd += __shfl_xor_sync(0xffffffffu, pd, o);
    }
    float inv = rsqrtf(s);
    if (lane == 0) {
        g_inv_norm[row] = inv;
        g_row_exp[row]  = 0.f;
        if (row < NS) g_posdot[row] = pd;
    }
    float scale = inv * SQRT2F;
    uint32_t* yq = (uint32_t*)(g_Yq + (size_t)row * DIM);
    float4* sy4 = (float4*)sY[wid];
    #pragma unroll
    for (int c = 0; c < 4; c++) {
        float4 y = make_float4(v[c].x * scale, v[c].y * scale, v[c].z * scale, v[c].w * scale);
        sy4[lane + 32 * c] = y;
        uint32_t lo = f2_e4m3x2(y.x, y.y);
        uint32_t hi = f2_e4m3x2(y.z, y.w);
        yq[lane + 32 * c] = lo | (hi << 16);
    }
    __syncthreads();
    // fused colsum: 256 threads, 2 cols each, sum over the block's 8 rows
    #pragma unroll
    for (int col = threadIdx.x; col < DIM; col += 256) {
        float t = 0.f;
        #pragma unroll
        for (int r = 0; r < 8; r++) t += sY[r][col];
        atomicAdd(&g_S[col], t);
    }
}

// ---------------- kernel 2: fp8 GEMM on UPPER-TRIANGULAR tiles --------------
// Off-diag tile (R<C): each exp(s_ij) feeds row_exp[i] AND row_exp[j] (symmetry).
// Diag tile: rows-only is complete. 3-stage cp.async, ONE sync per k-iter.
__global__ __launch_bounds__(256, 2) void gemm_kernel() {
    extern __shared__ __align__(128) char smem[];
    __shared__ float red[BM];    // per-row partials
    __shared__ float cred[BN];   // per-col partials (off-diag only)
    const uint32_t sb = smem_u32(smem);
    const int tid  = threadIdx.x, lane = tid & 31, wid = tid >> 5;
    const int wm   = wid & 3, wn = wid >> 2;

    // triangular decode: k -> (bx, by), by <= bx
    const int k = blockIdx.x;
    int bx = (int)((sqrtf(8.0f * (float)k + 1.0f) - 1.0f) * 0.5f);
    while ((bx + 1) * (bx + 2) / 2 <= k) bx++;
    while (bx * (bx + 1) / 2 > k)       bx--;
    const int by = k - bx * (bx + 1) / 2;
    const int row0 = by * BM, col0 = bx * BN;
    const bool offdiag = (bx != by);

    const int lr  = tid >> 1;
    const int lc0 = (tid & 1) * 2;
    const char* a_gsrc = (const char*)(g_Yq + (size_t)(row0 + lr) * DIM) + lc0 * 16;
    const char* b_gsrc = (const char*)(g_Yq + (size_t)(col0 + lr) * DIM) + lc0 * 16;
    const uint32_t adst0 = swz(lr, lc0), adst1 = swz(lr, lc0 + 1);

    float acc[2][8][4];
    #pragma unroll
    for (int mi = 0; mi < 2; mi++)
        #pragma unroll
        for (int ni = 0; ni < 8; ni++)
            #pragma unroll
            for (int c = 0; c < 4; c++) acc[mi][ni][c] = 0.f;

    // prologue: stages 0,1
    #pragma unroll
    for (int s = 0; s < 2; s++) {
        uint32_t Ab = sb + s * STAGE_BYTES, Bb = Ab + 8192;
        cp16(Ab + adst0, a_gsrc + s * BKB);
        cp16(Ab + adst1, a_gsrc + s * BKB + 16);
        cp16(Bb + adst0, b_gsrc + s * BKB);
        cp16(Bb + adst1, b_gsrc + s * BKB + 16);
        asm volatile("cp.async.commit_group;" ::: "memory");
    }

    for (int kc = 0; kc < NKC; kc++) {
        if (kc == NKC - 1) asm volatile("cp.async.wait_group 0;" ::: "memory");
        else               asm volatile("cp.async.wait_group 1;" ::: "memory");
        __syncthreads();   // data visible; stage (kc+2)%3 free (readers passed this barrier)
        if (kc + 2 < NKC) {
            uint32_t Ab = sb + ((kc + 2) % NSTAGE) * STAGE_BYTES, Bb = Ab + 8192;
            const char* as = a_gsrc + (size_t)(kc + 2) * BKB;
            const char* bs = b_gsrc + (size_t)(kc + 2) * BKB;
            cp16(Ab + adst0, as);
            cp16(Ab + adst1, as + 16);
            cp16(Bb + adst0, bs);
            cp16(Bb + adst1, bs + 16);
            asm volatile("cp.async.commit_group;" ::: "memory");
        }
        const uint32_t Ab = sb + (kc % NSTAGE) * STAGE_BYTES, Bb = Ab + 8192;
        const int lrow = (lane & 7) + ((lane >> 3) & 1) * 8;
        #pragma unroll
        for (int ks = 0; ks < 2; ks++) {
            const int lchk = ks * 2 + (lane >> 4);
            uint32_t a[2][4];
            #pragma unroll
            for (int mi = 0; mi < 2; mi++)
                ldm_x4(a[mi], Ab + swz(wm * 32 + mi * 16 + lrow, lchk));
            uint32_t b[8][2];
            #pragma unroll
            for (int np = 0; np < 4; np++) {
                uint32_t t4[4];
                ldm_x4(t4, Bb + swz(wn * 64 + np * 16 + lrow, lchk));
                b[np * 2][0]     = t4[0]; b[np * 2][1]     = t4[2];
                b[np * 2 + 1][0] = t4[1]; b[np * 2 + 1][1] = t4[3];
            }
            #pragma unroll
            for (int mi = 0; mi < 2; mi++)
                #pragma unroll
                for (int ni = 0; ni < 8; ni++)
                    mma_fp8(acc[mi][ni], a[mi], b[ni]);
        }
    }

    // ---- epilogue: exp once, feed row partials (+ col partials if offdiag) --
    __syncthreads();
    if (tid < BM) { red[tid] = 0.f; cred[tid] = 0.f; }
    __syncthreads();
    const int rloc  = wm * 32 + (lane >> 2);
    const int cbase = col0 + wn * 64 + 2 * (lane & 3);
    float ccol[16];
    #pragma unroll
    for (int t = 0; t < 16; t++) ccol[t] = 0.f;

    #pragma unroll
    for (int mi = 0; mi < 2; mi++) {
        #pragma unroll
        for (int h = 0; h < 2; h++) {
            const int il = rloc + mi * 16 + h * 8;
            const int i  = row0 + il;
            float e = 0.f;
            #pragma unroll
            for (int ni = 0; ni < 8; ni++) {
                #pragma unroll
                for (int q = 0; q < 2; q++) {
                    const int j = cbase + ni * 8 + q;
                    float s = acc[mi][ni][h * 2 + q];
                    float ex = (((i ^ j) & (NS - 1)) != 0) ? __expf(s) : 0.f;
                    e += ex;
                    ccol[ni * 2 + q] += ex;
                }
            }
            e += __shfl_xor_sync(0xffffffffu, e, 1);
            e += __shfl_xor_sync(0xffffffffu, e, 2);
            if ((lane & 3) == 0) atomicAdd(&red[il], e);
        }
    }
    if (offdiag) {
        #pragma unroll
        for (int ni = 0; ni < 8; ni++) {
            #pragma unroll
            for (int q = 0; q < 2; q++) {
                float c = ccol[ni * 2 + q];
                c += __shfl_xor_sync(0xffffffffu, c, 4);
                c += __shfl_xor_sync(0xffffffffu, c, 8);
                c += __shfl_xor_sync(0xffffffffu, c, 16);
                if ((lane >> 2) == 0)                       // lanes 0..3
                    atomicAdd(&cred[wn * 64 + ni * 8 + 2 * lane + q], c);
            }
        }
    }
    __syncthreads();
    if (tid < BM) {
        atomicAdd(&g_row_exp[row0 + tid], red[tid]);
        if (offdiag) atomicAdd(&g_row_exp[col0 + tid], cred[tid]);
    }
}

// ---------------- kernel 3: per-row finalize (rowdot + loss) ----------------
// s_ii = y.y = 2 exactly (y = x * rsqrt(x.x) * sqrt2), so only d = y.S needed.
__global__ void final_row_kernel(const float* __restrict__ x1, const float* __restrict__ x2) {
    __shared__ float r[24];
    int row  = blockIdx.x * 8 + (threadIdx.x >> 5);
    int wid  = threadIdx.x >> 5;
    int lane = threadIdx.x & 31;
    float scale = g_inv_norm[row] * SQRT2F;
    const float4* xr = (const float4*)row_ptr(x1, x2, row);
    const float4* S4 = (const float4*)g_S;
    float d = 0.f;
    #pragma unroll
    for (int c = 0; c < 4; c++) {
        float4 v = xr[lane + 32 * c];
        float4 sc = S4[lane + 32 * c];
        d += v.x * sc.x + v.y * sc.y + v.z * sc.z + v.w * sc.w;
    }
    #pragma unroll
    for (int o = 16; o; o >>= 1) d += __shfl_xor_sync(0xffffffffu, d, o);
    if (lane == 0) {
        d *= scale;                                        // y_i . S
        float sp = 2.0f * g_posdot[row & (NS - 1)] * g_inv_norm[row] * g_inv_norm[row ^ NS];
        float denom = __expf(sp) + g_row_exp[row] + 2.0f;  // +2 = exp(0) at 2 masked entries
        r[wid]      = __logf(denom) - sp;
        r[8 + wid]  = sp;
        r[16 + wid] = d - 2.0f - sp;                       // exact neg-sim row sum
    }
    __syncthreads();
    if (threadIdx.x == 0) {
        float L = 0.f, P = 0.f, NN = 0.f;
        #pragma unroll
        for (int k = 0; k < 8; k++) { L += r[k]; P += r[8 + k]; NN += r[16 + k]; }
        atomicAdd(&g_acc[0], L);
        atomicAdd(&g_acc[1], P);
        atomicAdd(&g_acc[2], NN);
    }
}
__global__ void finalize_write(float* __restrict__ out) {
    out[0] = g_acc[0] / (float)NTOT;
    out[1] = g_acc[1] / (float)NTOT;
    out[2] = g_acc[2] / (float)((double)NTOT * (double)NTOT - 2.0 * (double)NTOT);
}

extern "C" void kernel_launch(void* const* d_in, const int* in_sizes, int n_in,
                              void* d_out, int out_size) {
    const float* x1 = (const float*)d_in[0];
    const float* x2 = (const float*)d_in[1];
    cudaFuncSetAttribute(gemm_kernel, cudaFuncAttributeMaxDynamicSharedMemorySize, SMEM_DYN);
    zero_kernel<<<1, 512>>>();
    prep_kernel<<<NTOT / 8, 256>>>(x1, x2);
    gemm_kernel<<<NTILE, 256, SMEM_DYN>>>();
    final_row_kernel<<<NTOT / 8, 256>>>(x1, x2);
    finalize_write<<<1, 1>>>((float*)d_out);
}

// round 9
// speedup vs baseline: 2.6232x; 1.0888x over previous
#include <cuda_runtime.h>
#include <cuda_bf16.h>
#include <cstdint>
#include <math.h>

#define NS    4096
#define NTOT  8192
#define DIM   512
#define BM    128
#define BN    128
#define BKB   128             // k-chunk in bytes (= 128 fp8 elems)
#define NKC   (DIM / BKB)     // 4 k-chunks
#define SQRT2F 1.41421356237f
#define ASTAGE 16384          // 128 rows * 128B
#define STAGE_BYTES (2 * ASTAGE)
#define NSTAGE 3
#define SMEM_DYN (NSTAGE * STAGE_BYTES)   // 96KB
#define NTILE (64 * 65 / 2)   // triangular tiles

// ---------------- scratch (__device__ globals; no allocation allowed) -------
__device__ __align__(16) uint8_t g_Yq[NTOT * DIM];   // e4m3(normalized * sqrt2)
__device__ float g_inv_norm[NTOT];
__device__ float g_row_exp[NTOT];
__device__ float g_posdot[NS];
__device__ float g_S[DIM];
__device__ float g_acc[3];

// ---------------- PTX helpers (baseline PTX only) ---------------------------
__device__ __forceinline__ uint32_t smem_u32(const void* p) {
    uint32_t a;
    asm("{ .reg .u64 t; cvta.to.shared.u64 t, %1; cvt.u32.u64 %0, t; }" : "=r"(a) : "l"(p));
    return a;
}
__device__ __forceinline__ void cp16(uint32_t dst, const void* src) {
    asm volatile("cp.async.cg.shared.global [%0], [%1], 16;" :: "r"(dst), "l"(src) : "memory");
}
__device__ __forceinline__ void ldm_x4(uint32_t* r, uint32_t addr) {
    asm volatile("ldmatrix.sync.aligned.m8n8.x4.shared.b16 {%0,%1,%2,%3}, [%4];"
                 : "=r"(r[0]), "=r"(r[1]), "=r"(r[2]), "=r"(r[3]) : "r"(addr));
}
__device__ __forceinline__ void mma_fp8(float* d, const uint32_t* a, const uint32_t* b) {
    asm volatile(
        "mma.sync.aligned.m16n8k32.row.col.f32.e4m3.e4m3.f32 "
        "{%0,%1,%2,%3}, {%4,%5,%6,%7}, {%8,%9}, {%0,%1,%2,%3};"
        : "+f"(d[0]), "+f"(d[1]), "+f"(d[2]), "+f"(d[3])
        : "r"(a[0]), "r"(a[1]), "r"(a[2]), "r"(a[3]), "r"(b[0]), "r"(b[1]));
}
__device__ __forceinline__ uint16_t f2_e4m3x2(float lo, float hi) {
    uint16_t r;
    asm("cvt.rn.satfinite.e4m3x2.f32 %0, %1, %2;" : "=h"(r) : "f"(hi), "f"(lo));
    return r;
}
// SW128 swizzle for 128B rows: row r, 16B chunk c (0..7). Bank16 = c ^ (r&7):
// distinct across any 8 consecutive rows -> conflict-free ldmatrix phases.
__device__ __forceinline__ uint32_t swz(int r, int c) {
    return (uint32_t)(r * 128 + ((c ^ (r & 7)) << 4));
}
__device__ __forceinline__ const float* row_ptr(const float* x1, const float* x2, int r) {
    return (r < NS) ? (x1 + (size_t)r * DIM) : (x2 + (size_t)(r - NS) * DIM);
}

// ---------------- kernel 0: zero global accumulators ------------------------
__global__ void zero_kernel() {
    int t = threadIdx.x;
    if (t < DIM) g_S[t] = 0.f;
    if (t < 3)   g_acc[t] = 0.f;
}

// ---------------- kernel 1: norms + fp8 Y + posdot + fused colsum -----------
__global__ void prep_kernel(const float* __restrict__ x1, const float* __restrict__ x2) {
    __shared__ float sY[8][DIM];
    int wid  = threadIdx.x >> 5;
    int lane = threadIdx.x & 31;
    int row  = blockIdx.x * 8 + wid;
    const float4* xr = (const float4*)row_ptr(x1, x2, row);
    float4 v[4];
    float s = 0.f;
    #pragma unroll
    for (int c = 0; c < 4; c++) {
        v[c] = xr[lane + 32 * c];
        s += v[c].x * v[c].x + v[c].y * v[c].y + v[c].z * v[c].z + v[c].w * v[c].w;
    }
    float pd = 0.f;
    if (row < NS) {
        const float4* wr = (const float4*)(x2 + (size_t)row * DIM);
        #pragma unroll
        for (int c = 0; c < 4; c++) {
            float4 w = wr[lane + 32 * c];
            pd += v[c].x * w.x + v[c].y * w.y + v[c].z * w.z + v[c].w * w.w;
        }
    }
    #pragma unroll
    for (int o = 16; o; o >>= 1) {
        s  += __shfl_xor_sync(0xffffffffu, s, o);
        pd += __shfl_xor_sync(0xffffffffu, pd, o);
    }
    float inv = rsqrtf(s);
    if (lane == 0) {
        g_inv_norm[row] = inv;
        g_row_exp[row]  = 0.f;
        if (row < NS) g_posdot[row] = pd;
    }
    float scale = inv * SQRT2F;
    uint32_t* yq = (uint32_t*)(g_Yq + (size_t)row * DIM);
    float4* sy4 = (float4*)sY[wid];
    #pragma unroll
    for (int c = 0; c < 4; c++) {
        float4 y = make_float4(v[c].x * scale, v[c].y * scale, v[c].z * scale, v[c].w * scale);
        sy4[lane + 32 * c] = y;
        uint32_t lo = f2_e4m3x2(y.x, y.y);
        uint32_t hi = f2_e4m3x2(y.z, y.w);
        yq[lane + 32 * c] = lo | (hi << 16);
    }
    __syncthreads();
    #pragma unroll
    for (int col = threadIdx.x; col < DIM; col += 256) {
        float t = 0.f;
        #pragma unroll
        for (int r = 0; r < 8; r++) t += sY[r][col];
        atomicAdd(&g_S[col], t);
    }
}

// ---------------- kernel 2: fp8 GEMM on UPPER-TRIANGULAR tiles --------------
// BK=128 (4 chunks), 3-stage cp.async, split-B fragment pipelining.
__global__ __launch_bounds__(256, 2) void gemm_kernel() {
    extern __shared__ __align__(128) char smem[];
    __shared__ float red[BM];
    __shared__ float cred[BN];
    const uint32_t sb = smem_u32(smem);
    const int tid  = threadIdx.x, lane = tid & 31, wid = tid >> 5;
    const int wm   = wid & 3, wn = wid >> 2;

    const int k = blockIdx.x;
    int bx = (int)((sqrtf(8.0f * (float)k + 1.0f) - 1.0f) * 0.5f);
    while ((bx + 1) * (bx + 2) / 2 <= k) bx++;
    while (bx * (bx + 1) / 2 > k)       bx--;
    const int by = k - bx * (bx + 1) / 2;
    const int row0 = by * BM, col0 = bx * BN;
    const bool offdiag = (bx != by);

    // global->shared: thread t -> row t>>1, 4 chunks starting at (t&1)*4
    const int lr  = tid >> 1;
    const int lc0 = (tid & 1) * 4;
    const char* a_gsrc = (const char*)(g_Yq + (size_t)(row0 + lr) * DIM) + lc0 * 16;
    const char* b_gsrc = (const char*)(g_Yq + (size_t)(col0 + lr) * DIM) + lc0 * 16;
    uint32_t ad[4], bd[4];
    #pragma unroll
    for (int i = 0; i < 4; i++) { ad[i] = swz(lr, lc0 + i); bd[i] = ad[i]; }

    float acc[2][8][4];
    #pragma unroll
    for (int mi = 0; mi < 2; mi++)
        #pragma unroll
        for (int ni = 0; ni < 8; ni++)
            #pragma unroll
            for (int c = 0; c < 4; c++) acc[mi][ni][c] = 0.f;

    // prologue: stages 0,1
    #pragma unroll
    for (int s = 0; s < 2; s++) {
        uint32_t Ab = sb + s * STAGE_BYTES, Bb = Ab + ASTAGE;
        #pragma unroll
        for (int i = 0; i < 4; i++) {
            cp16(Ab + ad[i], a_gsrc + s * BKB + i * 16);
            cp16(Bb + bd[i], b_gsrc + s * BKB + i * 16);
        }
        asm volatile("cp.async.commit_group;" ::: "memory");
    }

    for (int kc = 0; kc < NKC; kc++) {
        if (kc == NKC - 1) asm volatile("cp.async.wait_group 0;" ::: "memory");
        else               asm volatile("cp.async.wait_group 1;" ::: "memory");
        __syncthreads();
        if (kc + 2 < NKC) {
            uint32_t Ab = sb + ((kc + 2) % NSTAGE) * STAGE_BYTES, Bb = Ab + ASTAGE;
            const char* as = a_gsrc + (size_t)(kc + 2) * BKB;
            const char* bs = b_gsrc + (size_t)(kc + 2) * BKB;
            #pragma unroll
            for (int i = 0; i < 4; i++) {
                cp16(Ab + ad[i], as + i * 16);
                cp16(Bb + bd[i], bs + i * 16);
            }
            asm volatile("cp.async.commit_group;" ::: "memory");
        }
        const uint32_t Ab = sb + (kc % NSTAGE) * STAGE_BYTES, Bb = Ab + ASTAGE;
        const int lrow = (lane & 7) + ((lane >> 3) & 1) * 8;
        #pragma unroll
        for (int ks = 0; ks < 4; ks++) {
            const int lchk = ks * 2 + (lane >> 4);
            uint32_t a[2][4];
            #pragma unroll
            for (int mi = 0; mi < 2; mi++)
                ldm_x4(a[mi], Ab + swz(wm * 32 + mi * 16 + lrow, lchk));
            // B half 0 (ni 0..3)
            uint32_t b0[4][2];
            #pragma unroll
            for (int np = 0; np < 2; np++) {
                uint32_t t4[4];
                ldm_x4(t4, Bb + swz(wn * 64 + np * 16 + lrow, lchk));
                b0[np * 2][0]     = t4[0]; b0[np * 2][1]     = t4[2];
                b0[np * 2 + 1][0] = t4[1]; b0[np * 2 + 1][1] = t4[3];
            }
            #pragma unroll
            for (int mi = 0; mi < 2; mi++)
                #pragma unroll
                for (int ni = 0; ni < 4; ni++)
                    mma_fp8(acc[mi][ni], a[mi], b0[ni]);
            // B half 1 (ni 4..7) loads overlap the MMAs above
            uint32_t b1[4][2];
            #pragma unroll
            for (int np = 0; np < 2; np++) {
                uint32_t t4[4];
                ldm_x4(t4, Bb + swz(wn * 64 + 32 + np * 16 + lrow, lchk));
                b1[np * 2][0]     = t4[0]; b1[np * 2][1]     = t4[2];
                b1[np * 2 + 1][0] = t4[1]; b1[np * 2 + 1][1] = t4[3];
            }
            #pragma unroll
            for (int mi = 0; mi < 2; mi++)
                #pragma unroll
                for (int ni = 0; ni < 4; ni++)
                    mma_fp8(acc[mi][ni + 4], a[mi], b1[ni]);
        }
    }

    // ---- epilogue: exp once, feed row partials (+ col partials if offdiag) --
    __syncthreads();
    if (tid < BM) { red[tid] = 0.f; cred[tid] = 0.f; }
    __syncthreads();
    const int rloc  = wm * 32 + (lane >> 2);
    const int cbase = col0 + wn * 64 + 2 * (lane & 3);
    float ccol[16];
    #pragma unroll
    for (int t = 0; t < 16; t++) ccol[t] = 0.f;

    #pragma unroll
    for (int mi = 0; mi < 2; mi++) {
        #pragma unroll
        for (int h = 0; h < 2; h++) {
            const int il = rloc + mi * 16 + h * 8;
            const int i  = row0 + il;
            float e = 0.f;
            #pragma unroll
            for (int ni = 0; ni < 8; ni++) {
                #pragma unroll
                for (int q = 0; q < 2; q++) {
                    const int j = cbase + ni * 8 + q;
                    float s = acc[mi][ni][h * 2 + q];
                    float ex = (((i ^ j) & (NS - 1)) != 0) ? __expf(s) : 0.f;
                    e += ex;
                    ccol[ni * 2 + q] += ex;
                }
            }
            e += __shfl_xor_sync(0xffffffffu, e, 1);
            e += __shfl_xor_sync(0xffffffffu, e, 2);
            if ((lane & 3) == 0) atomicAdd(&red[il], e);
        }
    }
    if (offdiag) {
        #pragma unroll
        for (int ni = 0; ni < 8; ni++) {
            #pragma unroll
            for (int q = 0; q < 2; q++) {
                float c = ccol[ni * 2 + q];
                c += __shfl_xor_sync(0xffffffffu, c, 4);
                c += __shfl_xor_sync(0xffffffffu, c, 8);
                c += __shfl_xor_sync(0xffffffffu, c, 16);
                if ((lane >> 2) == 0)
                    atomicAdd(&cred[wn * 64 + ni * 8 + 2 * lane + q], c);
            }
        }
    }
    __syncthreads();
    if (tid < BM) {
        atomicAdd(&g_row_exp[row0 + tid], red[tid]);
        if (offdiag) atomicAdd(&g_row_exp[col0 + tid], cred[tid]);
    }
}

// ---------------- kernel 3: per-row finalize (2 rows/warp, S in smem) -------
__global__ void final_row_kernel(const float* __restrict__ x1, const float* __restrict__ x2) {
    __shared__ float4 sS[DIM / 4];
    __shared__ float r[48];
    const int tid = threadIdx.x, wid = tid >> 5, lane = tid & 31;
    if (tid < DIM / 4) sS[tid] = ((const float4*)g_S)[tid];
    __syncthreads();

    const int r0 = blockIdx.x * 16 + wid * 2;
    const float4* xa = (const float4*)row_ptr(x1, x2, r0);
    const float4* xb = (const float4*)row_ptr(x1, x2, r0 + 1);
    float da = 0.f, db = 0.f;
    #pragma unroll
    for (int c = 0; c < 4; c++) {
        float4 va = xa[lane + 32 * c];
        float4 vb = xb[lane + 32 * c];
        float4 sc = sS[lane + 32 * c];
        da += va.x * sc.x + va.y * sc.y + va.z * sc.z + va.w * sc.w;
        db += vb.x * sc.x + vb.y * sc.y + vb.z * sc.z + vb.w * sc.w;
    }
    #pragma unroll
    for (int o = 16; o; o >>= 1) {
        da += __shfl_xor_sync(0xffffffffu, da, o);
        db += __shfl_xor_sync(0xffffffffu, db, o);
    }
    if (lane == 0) {
        float L = 0.f, P = 0.f, NN = 0.f;
        #pragma unroll
        for (int t = 0; t < 2; t++) {
            int row = r0 + t;
            float d = (t ? db : da) * g_inv_norm[row] * SQRT2F;   // y_i . S
            float sp = 2.0f * g_posdot[row & (NS - 1)] * g_inv_norm[row] * g_inv_norm[row ^ NS];
            float denom = __expf(sp) + g_row_exp[row] + 2.0f;
            L  += __logf(denom) - sp;
            P  += sp;
            NN += d - 2.0f - sp;   // s_ii = 2 exactly; exclude positive pair
        }
        r[wid] = L; r[16 + wid] = P; r[32 + wid] = NN;
    }
    __syncthreads();
    if (tid == 0) {
        float L = 0.f, P = 0.f, NN = 0.f;
        #pragma unroll
        for (int k = 0; k < 8; k++) { L += r[k]; P += r[16 + k]; NN += r[32 + k]; }
        atomicAdd(&g_acc[0], L);
        atomicAdd(&g_acc[1], P);
        atomicAdd(&g_acc[2], NN);
    }
}
__global__ void finalize_write(float* __restrict__ out) {
    out[0] = g_acc[0] / (float)NTOT;
    out[1] = g_acc[1] / (float)NTOT;
    out[2] = g_acc[2] / (float)((double)NTOT * (double)NTOT - 2.0 * (double)NTOT);
}

extern "C" void kernel_launch(void* const* d_in, const int* in_sizes, int n_in,
                              void* d_out, int out_size) {
    const float* x1 = (const float*)d_in[0];
    const float* x2 = (const float*)d_in[1];
    cudaFuncSetAttribute(gemm_kernel, cudaFuncAttributeMaxDynamicSharedMemorySize, SMEM_DYN);
    zero_kernel<<<1, 512>>>();
    prep_kernel<<<NTOT / 8, 256>>>(x1, x2);
    gemm_kernel<<<NTILE, 256, SMEM_DYN>>>();
    final_row_kernel<<<NTOT / 16, 256>>>(x1, x2);
    finalize_write<<<1, 1>>>((float*)d_out);
}

// round 10
// speedup vs baseline: 2.7113x; 1.0336x over previous
#include <cuda_runtime.h>
#include <cuda_bf16.h>
#include <cstdint>
#include <math.h>

#define NS    4096
#define NTOT  8192
#define DIM   512
#define BM    128
#define BN    128
#define BKB   128             // k-chunk in bytes (= 128 fp8 elems)
#define NKC   (DIM / BKB)     // 4 k-chunks
#define SQRT2F 1.41421356237f
#define ASTAGE 16384          // 128 rows * 128B
#define STAGE_BYTES (2 * ASTAGE)
#define NSTAGE 3
#define SMEM_DYN (NSTAGE * STAGE_BYTES)   // 96KB
#define NOFF  (64 * 63 / 2)   // strict lower-triangular (off-diag) tiles: 2016
#define NTILE (NOFF + 64)     // + 64 diagonal tiles, scheduled LAST

// ---------------- scratch (__device__ globals; no allocation allowed) -------
__device__ __align__(16) uint8_t g_Yq[NTOT * DIM];   // e4m3(normalized * sqrt2)
__device__ float g_inv_norm[NTOT];
__device__ float g_row_exp[NTOT];
__device__ float g_posdot[NS];
__device__ float g_S[DIM];          // zeroed by previous call's tail (static-init 0 first)
__device__ float g_acc[3];          // idem
__device__ unsigned int g_done;     // idem

// ---------------- PTX helpers (baseline PTX only) ---------------------------
__device__ __forceinline__ uint32_t smem_u32(const void* p) {
    uint32_t a;
    asm("{ .reg .u64 t; cvta.to.shared.u64 t, %1; cvt.u32.u64 %0, t; }" : "=r"(a) : "l"(p));
    return a;
}
__device__ __forceinline__ void cp16(uint32_t dst, const void* src) {
    asm volatile("cp.async.cg.shared.global [%0], [%1], 16;" :: "r"(dst), "l"(src) : "memory");
}
__device__ __forceinline__ void ldm_x4(uint32_t* r, uint32_t addr) {
    asm volatile("ldmatrix.sync.aligned.m8n8.x4.shared.b16 {%0,%1,%2,%3}, [%4];"
                 : "=r"(r[0]), "=r"(r[1]), "=r"(r[2]), "=r"(r[3]) : "r"(addr));
}
__device__ __forceinline__ void mma_fp8(float* d, const uint32_t* a, const uint32_t* b) {
    asm volatile(
        "mma.sync.aligned.m16n8k32.row.col.f32.e4m3.e4m3.f32 "
        "{%0,%1,%2,%3}, {%4,%5,%6,%7}, {%8,%9}, {%0,%1,%2,%3};"
        : "+f"(d[0]), "+f"(d[1]), "+f"(d[2]), "+f"(d[3])
        : "r"(a[0]), "r"(a[1]), "r"(a[2]), "r"(a[3]), "r"(b[0]), "r"(b[1]));
}
__device__ __forceinline__ uint16_t f2_e4m3x2(float lo, float hi) {
    uint16_t r;
    asm("cvt.rn.satfinite.e4m3x2.f32 %0, %1, %2;" : "=h"(r) : "f"(hi), "f"(lo));
    return r;
}
// SW128 swizzle for 128B rows: row r, 16B chunk c (0..7). Bank16 = c ^ (r&7):
// distinct across any 8 consecutive rows -> conflict-free ldmatrix phases.
__device__ __forceinline__ uint32_t swz(int r, int c) {
    return (uint32_t)(r * 128 + ((c ^ (r & 7)) << 4));
}
__device__ __forceinline__ const float* row_ptr(const float* x1, const float* x2, int r) {
    return (r < NS) ? (x1 + (size_t)r * DIM) : (x2 + (size_t)(r - NS) * DIM);
}

// ---------------- kernel 1: norms + fp8 Y + posdot + fused colsum -----------
// 2 rows per warp (8 front-batched LDG.128/thread), 16 rows/block, grid 512.
__global__ void prep_kernel(const float* __restrict__ x1, const float* __restrict__ x2) {
    __shared__ float sY[16][DIM];
    const int wid  = threadIdx.x >> 5;
    const int lane = threadIdx.x & 31;
    const int r0   = blockIdx.x * 16 + wid * 2;

    const float4* xa = (const float4*)row_ptr(x1, x2, r0);
    const float4* xb = (const float4*)row_ptr(x1, x2, r0 + 1);
    float4 va[4], vb[4];
    float sa = 0.f, sb = 0.f;
    #pragma unroll
    for (int c = 0; c < 4; c++) {
        va[c] = xa[lane + 32 * c];
        vb[c] = xb[lane + 32 * c];
    }
    #pragma unroll
    for (int c = 0; c < 4; c++) {
        sa += va[c].x * va[c].x + va[c].y * va[c].y + va[c].z * va[c].z + va[c].w * va[c].w;
        sb += vb[c].x * vb[c].x + vb[c].y * vb[c].y + vb[c].z * vb[c].z + vb[c].w * vb[c].w;
    }
    float pa = 0.f, pb = 0.f;
    if (r0 < NS) {                        // both rows < NS (NS multiple of 16)
        const float4* wa = (const float4*)(x2 + (size_t)r0 * DIM);
        const float4* wb = (const float4*)(x2 + (size_t)(r0 + 1) * DIM);
        #pragma unroll
        for (int c = 0; c < 4; c++) {
            float4 u = wa[lane + 32 * c], w = wb[lane + 32 * c];
            pa += va[c].x * u.x + va[c].y * u.y + va[c].z * u.z + va[c].w * u.w;
            pb += vb[c].x * w.x + vb[c].y * w.y + vb[c].z * w.z + vb[c].w * w.w;
        }
    }
    #pragma unroll
    for (int o = 16; o; o >>= 1) {
        sa += __shfl_xor_sync(0xffffffffu, sa, o);
        sb += __shfl_xor_sync(0xffffffffu, sb, o);
        pa += __shfl_xor_sync(0xffffffffu, pa, o);
        pb += __shfl_xor_sync(0xffffffffu, pb, o);
    }
    float inva = rsqrtf(sa), invb = rsqrtf(sb);
    if (lane == 0) {
        g_inv_norm[r0]     = inva;
        g_inv_norm[r0 + 1] = invb;
        g_row_exp[r0]      = 0.f;
        g_row_exp[r0 + 1]  = 0.f;
        if (r0 < NS) { g_posdot[r0] = pa; g_posdot[r0 + 1] = pb; }
    }
    inva = __shfl_sync(0xffffffffu, inva, 0);
    invb = __shfl_sync(0xffffffffu, invb, 0);
    const float ka = inva * SQRT2F, kb = invb * SQRT2F;
    uint32_t* ya = (uint32_t*)(g_Yq + (size_t)r0 * DIM);
    uint32_t* yb = (uint32_t*)(g_Yq + (size_t)(r0 + 1) * DIM);
    float4* s4a = (float4*)sY[wid * 2];
    float4* s4b = (float4*)sY[wid * 2 + 1];
    #pragma unroll
    for (int c = 0; c < 4; c++) {
        float4 yA = make_float4(va[c].x * ka, va[c].y * ka, va[c].z * ka, va[c].w * ka);
        float4 yB = make_float4(vb[c].x * kb, vb[c].y * kb, vb[c].z * kb, vb[c].w * kb);
        s4a[lane + 32 * c] = yA;
        s4b[lane + 32 * c] = yB;
        ya[lane + 32 * c] = (uint32_t)f2_e4m3x2(yA.x, yA.y) | ((uint32_t)f2_e4m3x2(yA.z, yA.w) << 16);
        yb[lane + 32 * c] = (uint32_t)f2_e4m3x2(yB.x, yB.y) | ((uint32_t)f2_e4m3x2(yB.z, yB.w) << 16);
    }
    __syncthreads();
    #pragma unroll
    for (int col = threadIdx.x; col < DIM; col += 256) {
        float t = 0.f;
        #pragma unroll
        for (int r = 0; r < 16; r++) t += sY[r][col];
        atomicAdd(&g_S[col], t);
    }
}

// ---------------- kernel 2: fp8 GEMM on triangular tiles (diag LAST) --------
__global__ __launch_bounds__(256, 2) void gemm_kernel() {
    extern __shared__ __align__(128) char smem[];
    __shared__ float red[BM];
    __shared__ float cred[BN];
    const uint32_t sb = smem_u32(smem);
    const int tid  = threadIdx.x, lane = tid & 31, wid = tid >> 5;
    const int wm   = wid & 3, wn = wid >> 2;

    // tile decode: k < NOFF -> strict lower pair (bx > by); else diagonal tile.
    const int k = blockIdx.x;
    int bx, by;
    const bool offdiag = (k < NOFF);
    if (offdiag) {
        bx = (int)((sqrtf(8.0f * (float)k + 1.0f) + 1.0f) * 0.5f);
        while (bx * (bx - 1) / 2 > k)        bx--;
        while ((bx + 1) * bx / 2 <= k)       bx++;
        by = k - bx * (bx - 1) / 2;
    } else {
        bx = by = k - NOFF;
    }
    const int row0 = by * BM, col0 = bx * BN;

    const int lr  = tid >> 1;
    const int lc0 = (tid & 1) * 4;
    const char* a_gsrc = (const char*)(g_Yq + (size_t)(row0 + lr) * DIM) + lc0 * 16;
    const char* b_gsrc = (const char*)(g_Yq + (size_t)(col0 + lr) * DIM) + lc0 * 16;
    uint32_t ad[4];
    #pragma unroll
    for (int i = 0; i < 4; i++) ad[i] = swz(lr, lc0 + i);

    float acc[2][8][4];
    #pragma unroll
    for (int mi = 0; mi < 2; mi++)
        #pragma unroll
        for (int ni = 0; ni < 8; ni++)
            #pragma unroll
            for (int c = 0; c < 4; c++) acc[mi][ni][c] = 0.f;

    #pragma unroll
    for (int s = 0; s < 2; s++) {
        uint32_t Ab = sb + s * STAGE_BYTES, Bb = Ab + ASTAGE;
        #pragma unroll
        for (int i = 0; i < 4; i++) {
            cp16(Ab + ad[i], a_gsrc + s * BKB + i * 16);
            cp16(Bb + ad[i], b_gsrc + s * BKB + i * 16);
        }
        asm volatile("cp.async.commit_group;" ::: "memory");
    }

    for (int kc = 0; kc < NKC; kc++) {
        if (kc == NKC - 1) asm volatile("cp.async.wait_group 0;" ::: "memory");
        else               asm volatile("cp.async.wait_group 1;" ::: "memory");
        __syncthreads();
        if (kc + 2 < NKC) {
            uint32_t Ab = sb + ((kc + 2) % NSTAGE) * STAGE_BYTES, Bb = Ab + ASTAGE;
            const char* as = a_gsrc + (size_t)(kc + 2) * BKB;
            const char* bs = b_gsrc + (size_t)(kc + 2) * BKB;
            #pragma unroll
            for (int i = 0; i < 4; i++) {
                cp16(Ab + ad[i], as + i * 16);
                cp16(Bb + ad[i], bs + i * 16);
            }
            asm volatile("cp.async.commit_group;" ::: "memory");
        }
        const uint32_t Ab = sb + (kc % NSTAGE) * STAGE_BYTES, Bb = Ab + ASTAGE;
        const int lrow = (lane & 7) + ((lane >> 3) & 1) * 8;
        #pragma unroll
        for (int ks = 0; ks < 4; ks++) {
            const int lchk = ks * 2 + (lane >> 4);
            uint32_t a[2][4];
            #pragma unroll
            for (int mi = 0; mi < 2; mi++)
                ldm_x4(a[mi], Ab + swz(wm * 32 + mi * 16 + lrow, lchk));
            uint32_t b0[4][2];
            #pragma unroll
            for (int np = 0; np < 2; np++) {
                uint32_t t4[4];
                ldm_x4(t4, Bb + swz(wn * 64 + np * 16 + lrow, lchk));
                b0[np * 2][0]     = t4[0]; b0[np * 2][1]     = t4[2];
                b0[np * 2 + 1][0] = t4[1]; b0[np * 2 + 1][1] = t4[3];
            }
            #pragma unroll
            for (int mi = 0; mi < 2; mi++)
                #pragma unroll
                for (int ni = 0; ni < 4; ni++)
                    mma_fp8(acc[mi][ni], a[mi], b0[ni]);
            uint32_t b1[4][2];
            #pragma unroll
            for (int np = 0; np < 2; np++) {
                uint32_t t4[4];
                ldm_x4(t4, Bb + swz(wn * 64 + 32 + np * 16 + lrow, lchk));
                b1[np * 2][0]     = t4[0]; b1[np * 2][1]     = t4[2];
                b1[np * 2 + 1][0] = t4[1]; b1[np * 2 + 1][1] = t4[3];
            }
            #pragma unroll
            for (int mi = 0; mi < 2; mi++)
                #pragma unroll
                for (int ni = 0; ni < 4; ni++)
                    mma_fp8(acc[mi][ni + 4], a[mi], b1[ni]);
        }
    }

    // ---- epilogue ----
    __syncthreads();
    if (tid < BM) { red[tid] = 0.f; cred[tid] = 0.f; }
    __syncthreads();
    const int rloc  = wm * 32 + (lane >> 2);
    const int cbase = col0 + wn * 64 + 2 * (lane & 3);
    float ccol[16];
    #pragma unroll
    for (int t = 0; t < 16; t++) ccol[t] = 0.f;

    #pragma unroll
    for (int mi = 0; mi < 2; mi++) {
        #pragma unroll
        for (int h = 0; h < 2; h++) {
            const int il = rloc + mi * 16 + h * 8;
            const int i  = row0 + il;
            float e = 0.f;
            #pragma unroll
            for (int ni = 0; ni < 8; ni++) {
                #pragma unroll
                for (int q = 0; q < 2; q++) {
                    const int j = cbase + ni * 8 + q;
                    float s = acc[mi][ni][h * 2 + q];
                    float ex = (((i ^ j) & (NS - 1)) != 0) ? __expf(s) : 0.f;
                    e += ex;
                    ccol[ni * 2 + q] += ex;
                }
            }
            e += __shfl_xor_sync(0xffffffffu, e, 1);
            e += __shfl_xor_sync(0xffffffffu, e, 2);
            if ((lane & 3) == 0) atomicAdd(&red[il], e);
        }
    }
    if (offdiag) {
        #pragma unroll
        for (int ni = 0; ni < 8; ni++) {
            #pragma unroll
            for (int q = 0; q < 2; q++) {
                float c = ccol[ni * 2 + q];
                c += __shfl_xor_sync(0xffffffffu, c, 4);
                c += __shfl_xor_sync(0xffffffffu, c, 8);
                c += __shfl_xor_sync(0xffffffffu, c, 16);
                if ((lane >> 2) == 0)
                    atomicAdd(&cred[wn * 64 + ni * 8 + 2 * lane + q], c);
            }
        }
    }
    __syncthreads();
    if (tid < BM) {
        atomicAdd(&g_row_exp[row0 + tid], red[tid]);
        if (offdiag) atomicAdd(&g_row_exp[col0 + tid], cred[tid]);
    }
}

// ---------------- kernel 3: finalize (rowdot + loss + output + reset) -------
// 2 rows/warp; last finishing block writes d_out and zeroes g_S/g_acc/g_done
// so the next graph replay starts from clean state (statics init to 0).
__global__ void final_row_kernel(const float* __restrict__ x1, const float* __restrict__ x2,
                                 float* __restrict__ out) {
    __shared__ float4 sS[DIM / 4];
    __shared__ float r[48];
    __shared__ int last;
    const int tid = threadIdx.x, wid = tid >> 5, lane = tid & 31;
    if (tid < DIM / 4) sS[tid] = ((const float4*)g_S)[tid];
    __syncthreads();

    const int r0 = blockIdx.x * 16 + wid * 2;
    const float4* xa = (const float4*)row_ptr(x1, x2, r0);
    const float4* xb = (const float4*)row_ptr(x1, x2, r0 + 1);
    float da = 0.f, db = 0.f;
    #pragma unroll
    for (int c = 0; c < 4; c++) {
        float4 va = xa[lane + 32 * c];
        float4 vb = xb[lane + 32 * c];
        float4 sc = sS[lane + 32 * c];
        da += va.x * sc.x + va.y * sc.y + va.z * sc.z + va.w * sc.w;
        db += vb.x * sc.x + vb.y * sc.y + vb.z * sc.z + vb.w * sc.w;
    }
    #pragma unroll
    for (int o = 16; o; o >>= 1) {
        da += __shfl_xor_sync(0xffffffffu, da, o);
        db += __shfl_xor_sync(0xffffffffu, db, o);
    }
    if (lane == 0) {
        float L = 0.f, P = 0.f, NN = 0.f;
        #pragma unroll
        for (int t = 0; t < 2; t++) {
            int row = r0 + t;
            float d  = (t ? db : da) * g_inv_norm[row] * SQRT2F;   // y_i . S
            float sp = 2.0f * g_posdot[row & (NS - 1)] * g_inv_norm[row] * g_inv_norm[row ^ NS];
            float denom = __expf(sp) + g_row_exp[row] + 2.0f;      // +2 = masked exp(0)s
            L  += __logf(denom) - sp;
            P  += sp;
            NN += d - 2.0f - sp;   // s_ii = 2 exactly; exclude positive pair
        }
        r[wid] = L; r[16 + wid] = P; r[32 + wid] = NN;
    }
    __syncthreads();
    if (tid == 0) {
        float L = 0.f, P = 0.f, NN = 0.f;
        #pragma unroll
        for (int k = 0; k < 8; k++) { L += r[k]; P += r[16 + k]; NN += r[32 + k]; }
        atomicAdd(&g_acc[0], L);
        atomicAdd(&g_acc[1], P);
        atomicAdd(&g_acc[2], NN);
        __threadfence();
        unsigned int prev = atomicAdd(&g_done, 1u);
        last = (prev == (unsigned int)(gridDim.x - 1)) ? 1 : 0;
    }
    __syncthreads();
    if (last) {
        if (tid == 0) {
            out[0] = g_acc[0] / (float)NTOT;
            out[1] = g_acc[1] / (float)NTOT;
            out[2] = g_acc[2] / (float)((double)NTOT * (double)NTOT - 2.0 * (double)NTOT);
            g_acc[0] = 0.f; g_acc[1] = 0.f; g_acc[2] = 0.f;
            g_done = 0u;
        }
        // cooperative reset of g_S for the next replay
        for (int c = tid; c < DIM; c += 256) g_S[c] = 0.f;
    }
}

extern "C" void kernel_launch(void* const* d_in, const int* in_sizes, int n_in,
                              void* d_out, int out_size) {
    const float* x1 = (const float*)d_in[0];
    const float* x2 = (const float*)d_in[1];
    cudaFuncSetAttribute(gemm_kernel, cudaFuncAttributeMaxDynamicSharedMemorySize, SMEM_DYN);
    prep_kernel<<<NTOT / 16, 256>>>(x1, x2);
    gemm_kernel<<<NTILE, 256, SMEM_DYN>>>();
    final_row_kernel<<<NTOT / 16, 256>>>(x1, x2, (float*)d_out);
}